// round 7
// baseline (speedup 1.0000x reference)
#include <cuda_runtime.h>

#define K     3
#define K2    9
#define PAD   1
#define Bn    2
#define Hn    352
#define Wn    1216
#define HW    (Hn * Wn)

#define TX    64
#define TY    4
#define HALO  5
#define TW    (TX + 2 * HALO)     // 74
#define TH    (TY + 2 * HALO)     // 14
#define TS    75                  // padded row stride (odd)

// Predicated global-memory bilinear (rare fallback path).
__device__ __forceinline__ float bilinear_global(const float* __restrict__ img,
                                                 int y0, int x0,
                                                 float ly, float lx) {
    int y1 = y0 + 1;
    int x1 = x0 + 1;
    bool yv0 = (unsigned)y0 < Hn;
    bool yv1 = (unsigned)y1 < Hn;
    bool xv0 = (unsigned)x0 < Wn;
    bool xv1 = (unsigned)x1 < Wn;

    float v00 = 0.f, v01 = 0.f, v10 = 0.f, v11 = 0.f;
    int base0 = y0 * Wn;
    int base1 = base0 + Wn;
    if (yv0 & xv0) v00 = __ldg(img + base0 + x0);
    if (yv0 & xv1) v01 = __ldg(img + base0 + x1);
    if (yv1 & xv0) v10 = __ldg(img + base1 + x0);
    if (yv1 & xv1) v11 = __ldg(img + base1 + x1);

    float top = fmaf(1.f - lx, v00, lx * v01);
    float bot = fmaf(1.f - lx, v10, lx * v11);
    return fmaf(1.f - ly, top, ly * bot);
}

__global__ __launch_bounds__(TX * TY, 5)
void postproc_deconv_kernel(const float* __restrict__ depth,
                            const float* __restrict__ weight,
                            const float* __restrict__ offset,
                            const float* __restrict__ wker,
                            const float* __restrict__ bias,
                            float* __restrict__ out) {
    __shared__ float tile[TH * TS];

    int tx  = threadIdx.x;                 // 0..63
    int ty  = threadIdx.y;                 // 0..3
    int tid = ty * TX + tx;
    int bx0 = blockIdx.x * TX;
    int by0 = blockIdx.y * TY;
    int b   = blockIdx.z;

    const float* dplane = depth + b * HW;
    int ox = bx0 - HALO;
    int oy = by0 - HALO;

    // ---- cooperative zero-padded depth tile load ----
    #pragma unroll
    for (int i = tid; i < TH * TW; i += TX * TY) {
        int r = i / TW;
        int c = i - r * TW;
        int gy = oy + r;
        int gx = ox + c;
        float v = 0.f;
        if (((unsigned)gy < Hn) & ((unsigned)gx < Wn))
            v = __ldg(dplane + gy * Wn + gx);
        tile[r * TS + c] = v;
    }
    __syncthreads();

    int x   = bx0 + tx;
    int y   = by0 + ty;
    int pix = y * Wn + x;
    const float* wbase = weight + b * (K2 * HW) + pix;
    const float* obase = offset + b * (2 * K2 * HW) + pix;

    // Fused: out = d + A - (ws/9)*S + bias
    float A = 0.f, S = 0.f, ws = 0.f;

    #pragma unroll
    for (int k = 0; k < K2; k++) {
        int kh = k / K;
        int kw = k % K;
        float wk = __ldg(wbase + k * HW);
        float dy = __ldg(obase + (2 * k)     * HW);
        float dx = __ldg(obase + (2 * k + 1) * HW);
        float wc = __ldg(wker + k);            // uniform broadcast, L1-hit

        float py = (float)(y - PAD + kh) + dy;
        float px = (float)(x - PAD + kw) + dx;
        float y0f = floorf(py);
        float x0f = floorf(px);
        float ly = py - y0f;
        float lx = px - x0f;
        int y0 = (int)y0f;
        int x0 = (int)x0f;

        int sy = y0 - oy;                      // tile-relative
        int sx = x0 - ox;

        float s;
        if (((unsigned)sy <= (TH - 2)) & ((unsigned)sx <= (TW - 2))) {
            // Fast path: whole 2x2 footprint inside tile (zeros pre-baked).
            const float* p = &tile[sy * TS + sx];
            float v00 = p[0];
            float v01 = p[1];
            float v10 = p[TS];
            float v11 = p[TS + 1];
            float top = fmaf(1.f - lx, v00, lx * v01);
            float bot = fmaf(1.f - lx, v10, lx * v11);
            s = fmaf(1.f - ly, top, ly * bot);
        } else {
            s = bilinear_global(dplane, y0, x0, ly, lx);
        }

        float t = wc * s;
        A  = fmaf(t, wk, A);
        S += t;
        ws += wk;
    }

    float d  = tile[(HALO + ty) * TS + (HALO + tx)];
    float bb = __ldg(bias);
    out[b * HW + pix] = d + A - (ws * (1.0f / 9.0f)) * S + bb;
}

extern "C" void kernel_launch(void* const* d_in, const int* in_sizes, int n_in,
                              void* d_out, int out_size) {
    const float* depth  = (const float*)d_in[0];
    const float* weight = (const float*)d_in[1];
    const float* offset = (const float*)d_in[2];
    const float* wker   = (const float*)d_in[3];
    const float* bias   = (const float*)d_in[4];
    float* out = (float*)d_out;

    dim3 block(TX, TY, 1);
    dim3 grid(Wn / TX, Hn / TY, Bn);       // 19 x 88 x 2
    postproc_deconv_kernel<<<grid, block>>>(depth, weight, offset, wker, bias, out);
}

// round 10
// speedup vs baseline: 1.3285x; 1.3285x over previous
#include <cuda_runtime.h>

#define K     3
#define K2    9
#define PAD   1
#define Bn    2
#define Hn    352
#define Wn    1216
#define HW    (Hn * Wn)

// Zero-padded depth plane: 1-px margin left/top, 3-px zero cols right (stride pad).
#define PH    (Hn + 2)            // 354
#define PW    1220                // >= Wn + 2, multiple of 4
#define PHW   (PH * PW)

__device__ float g_pad[Bn * PHW];

// Fill padded plane: P[b][r][c] = depth[b][r-1][c-1] for interior, else 0.
__global__ __launch_bounds__(256)
void pad_kernel(const float* __restrict__ depth) {
    int idx   = blockIdx.x * blockDim.x + threadIdx.x;   // over Bn*PH*(PW/4)
    int total = Bn * PH * (PW / 4);
    if (idx >= total) return;
    int q = idx % (PW / 4);
    int t = idx / (PW / 4);
    int r = t % PH;
    int b = t / PH;
    int y = r - 1;

    float4 v = make_float4(0.f, 0.f, 0.f, 0.f);
    if ((unsigned)y < Hn) {
        int c0 = q * 4;
        float* vv = &v.x;
        #pragma unroll
        for (int j = 0; j < 4; j++) {
            int x = c0 + j - 1;
            if ((unsigned)x < Wn) vv[j] = __ldg(depth + b * HW + y * Wn + x);
        }
    }
    *(float4*)(g_pad + b * PHW + r * PW + q * 4) = v;
}

// Branchless bilinear on the padded plane. basep points at P[b][1][1] (= pixel (0,0)).
// Float-clamp to [-1, Hn] x [-1, Wn]: exact vs reference (clamped side gets lerp
// weight 0 and lands on a zero margin row/col).
__device__ __forceinline__ float bilinear_pad(const float* __restrict__ basep,
                                              float py, float px) {
    float pyc = fminf(fmaxf(py, -1.f), (float)Hn);
    float pxc = fminf(fmaxf(px, -1.f), (float)Wn);
    float y0f = floorf(pyc);
    float x0f = floorf(pxc);
    float ly  = pyc - y0f;
    float lx  = pxc - x0f;
    int a = (int)y0f * PW + (int)x0f;     // y0 in [-1,Hn], x0 in [-1,Wn] -> in padded range

    float v00 = __ldg(basep + a);
    float v01 = __ldg(basep + a + 1);
    float v10 = __ldg(basep + a + PW);
    float v11 = __ldg(basep + a + PW + 1);

    float top = fmaf(1.f - lx, v00, lx * v01);
    float bot = fmaf(1.f - lx, v10, lx * v11);
    return fmaf(1.f - ly, top, ly * bot);
}

// Block (32,8): each thread handles 2 adjacent pixels (float2), tile = 64x8.
__global__ __launch_bounds__(256, 5)
void postproc_deconv_kernel(const float* __restrict__ depth,
                            const float* __restrict__ weight,
                            const float* __restrict__ offset,
                            const float* __restrict__ wker,
                            const float* __restrict__ bias,
                            float* __restrict__ out) {
    int x0 = blockIdx.x * 64 + threadIdx.x * 2;
    int y  = blockIdx.y * 8  + threadIdx.y;
    int b  = blockIdx.z;

    int pix = y * Wn + x0;                 // even -> 8B aligned
    const float* basep = g_pad + b * PHW + PW + 1;   // padded plane, origin at px(0,0)
    const float* wbase = weight + b * (K2 * HW) + pix;
    const float* obase = offset + b * (2 * K2 * HW) + pix;

    // Fused accumulators: out_j = d_j + A_j - (wsum_j/9)*S_j + bias
    float A0 = 0.f, A1 = 0.f, S0 = 0.f, S1 = 0.f, ws0 = 0.f, ws1 = 0.f;

    #pragma unroll
    for (int k = 0; k < K2; k++) {
        int kh = k / K;
        int kw = k % K;
        float2 wk2 = __ldg((const float2*)(wbase + k * HW));
        float2 dy2 = __ldg((const float2*)(obase + (2 * k)     * HW));
        float2 dx2 = __ldg((const float2*)(obase + (2 * k + 1) * HW));
        float wc = __ldg(wker + k);        // uniform broadcast, L1-hit

        float py_base = (float)(y - PAD + kh);
        float px_base = (float)(x0 - PAD + kw);

        float s0 = bilinear_pad(basep, py_base + dy2.x, px_base + dx2.x);
        float s1 = bilinear_pad(basep, py_base + dy2.y, px_base + 1.f + dx2.y);

        float t0 = wc * s0;
        float t1 = wc * s1;
        A0 = fmaf(t0, wk2.x, A0);
        A1 = fmaf(t1, wk2.y, A1);
        S0 += t0;
        S1 += t1;
        ws0 += wk2.x;
        ws1 += wk2.y;
    }

    float2 d2 = __ldg((const float2*)(depth + b * HW + pix));
    float bb  = __ldg(bias);
    const float inv9 = 1.0f / 9.0f;

    float2 o2;
    o2.x = d2.x + A0 - (ws0 * inv9) * S0 + bb;
    o2.y = d2.y + A1 - (ws1 * inv9) * S1 + bb;
    *(float2*)(out + b * HW + pix) = o2;
}

extern "C" void kernel_launch(void* const* d_in, const int* in_sizes, int n_in,
                              void* d_out, int out_size) {
    const float* depth  = (const float*)d_in[0];
    const float* weight = (const float*)d_in[1];
    const float* offset = (const float*)d_in[2];
    const float* wker   = (const float*)d_in[3];
    const float* bias   = (const float*)d_in[4];
    float* out = (float*)d_out;

    int pad_total  = Bn * PH * (PW / 4);
    int pad_blocks = (pad_total + 255) / 256;
    pad_kernel<<<pad_blocks, 256>>>(depth);

    dim3 block(32, 8, 1);
    dim3 grid(Wn / 64, Hn / 8, Bn);
    postproc_deconv_kernel<<<grid, block>>>(depth, weight, offset, wker, bias, out);
}

// round 11
// speedup vs baseline: 1.4238x; 1.0717x over previous
#include <cuda_runtime.h>

#define K     3
#define K2    9
#define PAD   1
#define Bn    2
#define Hn    352
#define Wn    1216
#define HW    (Hn * Wn)

// Zero-padded depth plane.
// Rows: pad row r holds pixel row (r-1); rows 0 and 353..355 are zero. PH=356.
// Cols: left margin 4 (cols 0..3 zero), pixel x at col (x+4), cols 1220..1223 zero.
#define PH    356
#define PW    1224                // multiple of 4
#define MARG  4
#define PHW   (PH * PW)
#define PQ    (PW / 4)            // 306 quads per row

__device__ float g_pad[Bn * PHW];

// Aligned float4 copy: interior quads q=1..304 map to depth x0=4*(q-1) (16B aligned
// on both sides). Everything else is zero.
__global__ __launch_bounds__(256)
void pad_kernel(const float* __restrict__ depth) {
    int idx   = blockIdx.x * blockDim.x + threadIdx.x;   // over Bn*PH*PQ
    int total = Bn * PH * PQ;
    if (idx >= total) return;
    int q = idx % PQ;
    int t = idx / PQ;
    int r = t % PH;
    int b = t / PH;
    int y = r - 1;

    float4 v = make_float4(0.f, 0.f, 0.f, 0.f);
    if (((unsigned)y < Hn) & (q >= 1) & (q <= Wn / 4)) {
        v = __ldg((const float4*)(depth + b * HW + y * Wn + (q - 1) * 4));
    }
    *(float4*)(g_pad + b * PHW + r * PW + q * 4) = v;
}

// Branchless bilinear on the padded plane. basep points at pixel (0,0).
// Float-clamp to [-1, Hn] x [-1, Wn]: exact vs reference (clamped side gets lerp
// weight 0 and lands on a zero margin row/col). Max footprint: row 1+352+1=354<356,
// col 4+1216+1=1221<1224 — always in-bounds.
__device__ __forceinline__ float bilinear_pad(const float* __restrict__ basep,
                                              float py, float px) {
    float pyc = fminf(fmaxf(py, -1.f), (float)Hn);
    float pxc = fminf(fmaxf(px, -1.f), (float)Wn);
    float y0f = floorf(pyc);
    float x0f = floorf(pxc);
    float ly  = pyc - y0f;
    float lx  = pxc - x0f;
    int a = (int)y0f * PW + (int)x0f;

    float v00 = __ldg(basep + a);
    float v01 = __ldg(basep + a + 1);
    float v10 = __ldg(basep + a + PW);
    float v11 = __ldg(basep + a + PW + 1);

    float top = fmaf(1.f - lx, v00, lx * v01);
    float bot = fmaf(1.f - lx, v10, lx * v11);
    return fmaf(1.f - ly, top, ly * bot);
}

// Block (32,8): each thread handles 2 adjacent pixels (float2), tile = 64x8.
// min-blocks 4 -> 64-reg budget: enough registers for ptxas to front-batch
// loads (MLP) — R10 showed 48 regs exposes gather latency.
__global__ __launch_bounds__(256, 4)
void postproc_deconv_kernel(const float* __restrict__ depth,
                            const float* __restrict__ weight,
                            const float* __restrict__ offset,
                            const float* __restrict__ wker,
                            const float* __restrict__ bias,
                            float* __restrict__ out) {
    int x0 = blockIdx.x * 64 + threadIdx.x * 2;
    int y  = blockIdx.y * 8  + threadIdx.y;
    int b  = blockIdx.z;

    int pix = y * Wn + x0;                 // even -> 8B aligned
    const float* basep = g_pad + b * PHW + PW + MARG;   // pixel (0,0)
    const float* wbase = weight + b * (K2 * HW) + pix;
    const float* obase = offset + b * (2 * K2 * HW) + pix;

    // Hoist uniform conv weights + bias (L1-resident broadcast loads).
    float wc[K2];
    #pragma unroll
    for (int k = 0; k < K2; k++) wc[k] = __ldg(wker + k);
    float bb = __ldg(bias);

    // Fused accumulators: out_j = d_j + A_j - (wsum_j/9)*S_j + bias
    float A0 = 0.f, A1 = 0.f, S0 = 0.f, S1 = 0.f, ws0 = 0.f, ws1 = 0.f;

    #pragma unroll
    for (int k = 0; k < K2; k++) {
        int kh = k / K;
        int kw = k % K;
        float2 wk2 = __ldg((const float2*)(wbase + k * HW));
        float2 dy2 = __ldg((const float2*)(obase + (2 * k)     * HW));
        float2 dx2 = __ldg((const float2*)(obase + (2 * k + 1) * HW));

        float py_base = (float)(y - PAD + kh);
        float px_base = (float)(x0 - PAD + kw);

        float s0 = bilinear_pad(basep, py_base + dy2.x, px_base + dx2.x);
        float s1 = bilinear_pad(basep, py_base + dy2.y, px_base + 1.f + dx2.y);

        float t0 = wc[k] * s0;
        float t1 = wc[k] * s1;
        A0 = fmaf(t0, wk2.x, A0);
        A1 = fmaf(t1, wk2.y, A1);
        S0 += t0;
        S1 += t1;
        ws0 += wk2.x;
        ws1 += wk2.y;
    }

    float2 d2 = __ldg((const float2*)(depth + b * HW + pix));
    const float inv9 = 1.0f / 9.0f;

    float2 o2;
    o2.x = d2.x + A0 - (ws0 * inv9) * S0 + bb;
    o2.y = d2.y + A1 - (ws1 * inv9) * S1 + bb;
    *(float2*)(out + b * HW + pix) = o2;
}

extern "C" void kernel_launch(void* const* d_in, const int* in_sizes, int n_in,
                              void* d_out, int out_size) {
    const float* depth  = (const float*)d_in[0];
    const float* weight = (const float*)d_in[1];
    const float* offset = (const float*)d_in[2];
    const float* wker   = (const float*)d_in[3];
    const float* bias   = (const float*)d_in[4];
    float* out = (float*)d_out;

    int pad_total  = Bn * PH * PQ;
    int pad_blocks = (pad_total + 255) / 256;
    pad_kernel<<<pad_blocks, 256>>>(depth);

    dim3 block(32, 8, 1);
    dim3 grid(Wn / 64, Hn / 8, Bn);
    postproc_deconv_kernel<<<grid, block>>>(depth, weight, offset, wker, bias, out);
}

// round 12
// speedup vs baseline: 1.6165x; 1.1353x over previous
#include <cuda_runtime.h>

#define K     3
#define K2    9
#define PAD   1
#define Bn    2
#define Hn    352
#define Wn    1216
#define HW    (Hn * Wn)

__device__ __forceinline__ float bilinear_sample(const float* __restrict__ img,
                                                 float py, float px) {
    float y0f = floorf(py);
    float x0f = floorf(px);
    float ly  = py - y0f;
    float lx  = px - x0f;
    int y0 = (int)y0f;
    int x0 = (int)x0f;
    int y1 = y0 + 1;
    int x1 = x0 + 1;

    bool yv0 = (unsigned)y0 < Hn;
    bool yv1 = (unsigned)y1 < Hn;
    bool xv0 = (unsigned)x0 < Wn;
    bool xv1 = (unsigned)x1 < Wn;

    float v00 = 0.f, v01 = 0.f, v10 = 0.f, v11 = 0.f;
    int base0 = y0 * Wn;
    int base1 = base0 + Wn;
    if (yv0 & xv0) v00 = __ldg(img + base0 + x0);
    if (yv0 & xv1) v01 = __ldg(img + base0 + x1);
    if (yv1 & xv0) v10 = __ldg(img + base1 + x0);
    if (yv1 & xv1) v11 = __ldg(img + base1 + x1);

    float omly = 1.f - ly;
    float omlx = 1.f - lx;
    float top = fmaf(omlx, v00, lx * v01);
    float bot = fmaf(omlx, v10, lx * v11);
    return fmaf(omly, top, ly * bot);
}

// Block (32,8): each thread handles 2 adjacent pixels (float2), tile = 64x8.
// All 18 offset float2 loads are front-batched so the DRAM latency of the
// streaming loads is overlapped once, not staggered per-k.
__global__ __launch_bounds__(256, 4)
void postproc_deconv_kernel(const float* __restrict__ depth,
                            const float* __restrict__ weight,
                            const float* __restrict__ offset,
                            const float* __restrict__ wker,
                            const float* __restrict__ bias,
                            float* __restrict__ out) {
    int x0 = blockIdx.x * 64 + threadIdx.x * 2;
    int y  = blockIdx.y * 8  + threadIdx.y;
    int b  = blockIdx.z;

    int pix = y * Wn + x0;                 // even -> 8B aligned
    const float* dplane = depth  + b * HW;
    const float* wbase  = weight + b * (K2 * HW) + pix;
    const float* obase  = offset + b * (2 * K2 * HW) + pix;

    // ---- front-batch ALL offset loads (18 x float2 = 36 regs) ----
    float2 dyv[K2], dxv[K2];
    #pragma unroll
    for (int k = 0; k < K2; k++) {
        dyv[k] = __ldg((const float2*)(obase + (2 * k)     * HW));
        dxv[k] = __ldg((const float2*)(obase + (2 * k + 1) * HW));
    }

    // Streamed depth read also warms L1 lines the gathers will hit.
    float2 d2 = __ldg((const float2*)(dplane + pix));

    // Fused accumulators: out_j = d_j + A_j - (wsum_j/9)*S_j + bias
    float A0 = 0.f, A1 = 0.f, S0 = 0.f, S1 = 0.f, ws0 = 0.f, ws1 = 0.f;

    #pragma unroll
    for (int k = 0; k < K2; k++) {
        int kh = k / K;
        int kw = k % K;
        float2 wk2 = __ldg((const float2*)(wbase + k * HW));
        float wc = __ldg(wker + k);        // uniform broadcast, L1-hit

        float py_base = (float)(y - PAD + kh);
        float px_base = (float)(x0 - PAD + kw);

        float s0 = bilinear_sample(dplane, py_base + dyv[k].x, px_base + dxv[k].x);
        float s1 = bilinear_sample(dplane, py_base + dyv[k].y, px_base + 1.f + dxv[k].y);

        float t0 = wc * s0;
        float t1 = wc * s1;
        A0 = fmaf(t0, wk2.x, A0);
        A1 = fmaf(t1, wk2.y, A1);
        S0 += t0;
        S1 += t1;
        ws0 += wk2.x;
        ws1 += wk2.y;
    }

    float bb = __ldg(bias);
    const float inv9 = 1.0f / 9.0f;

    float2 o2;
    o2.x = d2.x + A0 - (ws0 * inv9) * S0 + bb;
    o2.y = d2.y + A1 - (ws1 * inv9) * S1 + bb;
    *(float2*)(out + b * HW + pix) = o2;
}

extern "C" void kernel_launch(void* const* d_in, const int* in_sizes, int n_in,
                              void* d_out, int out_size) {
    const float* depth  = (const float*)d_in[0];
    const float* weight = (const float*)d_in[1];
    const float* offset = (const float*)d_in[2];
    const float* wker   = (const float*)d_in[3];
    const float* bias   = (const float*)d_in[4];
    float* out = (float*)d_out;

    dim3 block(32, 8, 1);
    dim3 grid(Wn / 64, Hn / 8, Bn);
    postproc_deconv_kernel<<<grid, block>>>(depth, weight, offset, wker, bias, out);
}